// round 14
// baseline (speedup 1.0000x reference)
#include <cuda_runtime.h>
#include <cuda_bf16.h>
#include <cstdint>
#include <math.h>

// Problem constants
#define BB 8
#define CC 64
#define HWN 65536
#define NCHK 64                // chunks (1024 px each) for k12/k4
#define CHPX1 1024
#define SUBPX 256              // k12 smem subtile width

typedef unsigned long long ull;

// ---- k12 smem layout (floats) ----
#define K12_XS    0                     // 64*256 = 16384 floats
#define K12_ES    16384                 // 256
#define K12_RED   16640                 // 8
#define K12_SMEM  (16648 * 4)           // bytes

// ---- k5: X tile row = one channel, 64 px bf16 padded to 144 B ----
#define XROWB    144

// ---------------- scratch (device globals) -----------------------------------
__device__ float g_t[BB * HWN];           // pre-conv spatial attention
__device__ float g_s[BB * HWN];           // sigmoid(conv(t))
__device__ float g_Zpart[BB * NCHK];
__device__ float g_pooledpart[BB * NCHK * CC];
__device__ float g_a[BB * CC];            // channel softmax
__device__ float g_weff[BB * CC];         // a^T Wq
// Row-interleaved stacked A: tile w rows [16w,16w+8) = M1[8w..8w+8),
// rows [16w+8,16w+16) = M2[8w..8w+8). bf16x2 pair-packed over input channel.
__device__ uint32_t g_AH[BB * 128 * 32];  // hi part
__device__ uint32_t g_AL[BB * 128 * 32];  // lo part

// ---------------- mma.sync m16n8k16 bf16 -------------------------------------
#define MMA16816(d0, d1, d2, d3, a0, a1, a2, a3, b0, b1)                     \
    asm volatile(                                                            \
        "mma.sync.aligned.m16n8k16.row.col.f32.bf16.bf16.f32 "               \
        "{%0,%1,%2,%3}, {%4,%5,%6,%7}, {%8,%9}, {%0,%1,%2,%3};"              \
        : "+f"(d0), "+f"(d1), "+f"(d2), "+f"(d3)                             \
        : "r"(a0), "r"(a1), "r"(a2), "r"(a3), "r"(b0), "r"(b1))

__device__ __forceinline__ void ldsm_x4_trans(uint32_t& d0, uint32_t& d1,
                                              uint32_t& d2, uint32_t& d3,
                                              uint32_t saddr) {
    asm volatile(
        "ldmatrix.sync.aligned.m8n8.x4.trans.shared.b16 {%0,%1,%2,%3}, [%4];"
        : "=r"(d0), "=r"(d1), "=r"(d2), "=r"(d3) : "r"(saddr));
}

__device__ __forceinline__ uint32_t bfpack(float v0, float v1,
                                           float& l0, float& l1) {
    __nv_bfloat16 h0 = __float2bfloat16_rn(v0);
    __nv_bfloat16 h1 = __float2bfloat16_rn(v1);
    l0 = v0 - __bfloat162float(h0);
    l1 = v1 - __bfloat162float(h1);
    return (uint32_t)__bfloat16_as_ushort(h0) |
           ((uint32_t)__bfloat16_as_ushort(h1) << 16);
}
__device__ __forceinline__ uint32_t bfpack2(float v0, float v1) {
    return (uint32_t)__bfloat16_as_ushort(__float2bfloat16_rn(v0)) |
           ((uint32_t)__bfloat16_as_ushort(__float2bfloat16_rn(v1)) << 16);
}
// Truncation split: hi = top-16-bits of each fp32 (exact bf16), packed by PRMT.
// Result: low half = hi16(u0) (first pixel), high half = hi16(u1).
__device__ __forceinline__ uint32_t prmt_hi(uint32_t u0, uint32_t u1) {
    uint32_t r;
    asm("prmt.b32 %0, %1, %2, 0x7632;" : "=r"(r) : "r"(u0), "r"(u1));
    return r;
}
// d = { lo half = bf16(b), hi half = bf16(a) }
__device__ __forceinline__ uint32_t cvt_bf16x2(float hi, float lo) {
    uint32_t r;
    asm("cvt.rn.bf16x2.f32 %0, %1, %2;" : "=r"(r) : "f"(hi), "f"(lo));
    return r;
}
__device__ __forceinline__ float trunc_resid(float v) {
    return v - __uint_as_float(__float_as_uint(v) & 0xFFFF0000u);
}

// ---------------- K12: fused exp(k logits) + weighted pooling ----------------
__global__ void __launch_bounds__(256)
k12_fused(const float* __restrict__ x, const float* __restrict__ Wk) {
    extern __shared__ float sh[];
    float* xs  = sh + K12_XS;
    float* es  = sh + K12_ES;
    float* red = sh + K12_RED;
    __shared__ float wk[CC];

    const int b = blockIdx.y;
    const int chunk = blockIdx.x;
    const int base = chunk * CHPX1;
    const int tid = threadIdx.x;
    const int wid = tid >> 5, lid = tid & 31;
    if (tid < CC) wk[tid] = Wk[tid];

    const float* xb = x + (size_t)b * CC * HWN;
    float zacc = 0.f;
    float pacc[8];
    #pragma unroll
    for (int j = 0; j < 8; ++j) pacc[j] = 0.f;

    for (int s = 0; s < 4; ++s) {
        const int pbase = base + s * SUBPX;
        __syncthreads();
        #pragma unroll
        for (int i = tid; i < 4096; i += 256) {
            const int c = i >> 6, k = i & 63;
            ((float4*)(xs + c * SUBPX))[k] =
                __ldg((const float4*)(xb + (size_t)c * HWN + pbase) + k);
        }
        __syncthreads();
        float lg = 0.f;
        #pragma unroll 16
        for (int c = 0; c < CC; ++c)
            lg = fmaf(wk[c], xs[c * SUBPX + tid], lg);
        const float e = expf(lg);
        es[tid] = e;
        zacc += e;
        __syncthreads();
        #pragma unroll
        for (int j = 0; j < 8; ++j) {
            const int c = wid * 8 + j;
            const float4* xr = (const float4*)(xs + c * SUBPX);
            const float4* er = (const float4*)es;
            float a = 0.f;
            #pragma unroll
            for (int q = 0; q < 2; ++q) {
                const float4 v = xr[lid * 2 + q];
                const float4 e4 = er[lid * 2 + q];
                a += v.x * e4.x + v.y * e4.y + v.z * e4.z + v.w * e4.w;
            }
            pacc[j] += a;
        }
    }

    #pragma unroll
    for (int j = 0; j < 8; ++j) {
        #pragma unroll
        for (int off = 16; off; off >>= 1)
            pacc[j] += __shfl_xor_sync(0xffffffffu, pacc[j], off);
    }
    if (lid == 0) {
        #pragma unroll
        for (int j = 0; j < 8; ++j)
            g_pooledpart[((size_t)b * NCHK + chunk) * CC + wid * 8 + j] = pacc[j];
    }
    #pragma unroll
    for (int off = 16; off; off >>= 1)
        zacc += __shfl_xor_sync(0xffffffffu, zacc, off);
    if (lid == 0) red[wid] = zacc;
    __syncthreads();
    if (tid == 0) {
        float zz = 0.f;
        #pragma unroll
        for (int w = 0; w < 8; ++w) zz += red[w];
        g_Zpart[b * NCHK + chunk] = zz;
    }
}

// ---------------- K3: channel-attention chain --------------------------------
__global__ void k3_stats(const float* __restrict__ Wq, const float* __restrict__ Wup) {
    __shared__ float Wq_s[CC * CC];
    __shared__ float Wup_s[CC * CC];
    __shared__ float zs[BB];
    __shared__ float pooled[BB * CC];
    __shared__ float att[BB * CC];
    __shared__ float uu[BB * CC];
    __shared__ float as_[BB * CC];
    __shared__ float mx[BB];
    __shared__ float esum[BB];
    __shared__ float esv[BB * CC];
    const int tid = threadIdx.x;           // 512
    for (int i = tid; i < CC * CC / 4; i += 512) {
        ((float4*)Wq_s)[i]  = ((const float4*)Wq)[i];
        ((float4*)Wup_s)[i] = ((const float4*)Wup)[i];
    }
    const int b = tid >> 6, c = tid & 63;
    if (c == 0) {
        float z = 0.f;
        #pragma unroll 32
        for (int ch = 0; ch < NCHK; ++ch) z += g_Zpart[b * NCHK + ch];
        zs[b] = z;
    }
    {
        float s = 0.f;
        #pragma unroll 32
        for (int ch = 0; ch < NCHK; ++ch)
            s += g_pooledpart[((size_t)b * NCHK + ch) * CC + c];
        pooled[tid] = s;
    }
    __syncthreads();
    const float inv = 1.f / zs[b];
    {
        float s = 0.f;
        #pragma unroll 16
        for (int i = 0; i < CC; ++i) s = fmaf(Wq_s[c * CC + i], pooled[b * CC + i], s);
        att[tid] = s * inv;
    }
    __syncthreads();
    {
        float s = 0.f;
        #pragma unroll 16
        for (int i = 0; i < CC; ++i) s = fmaf(Wup_s[c * CC + i], att[b * CC + i], s);
        uu[tid] = s;
    }
    __syncthreads();
    if (c == 0) {
        float m = -3.4e38f;
        #pragma unroll 16
        for (int i = 0; i < CC; ++i) m = fmaxf(m, uu[b * CC + i]);
        mx[b] = m;
    }
    __syncthreads();
    esv[tid] = expf(uu[tid] - mx[b]);
    __syncthreads();
    if (c == 0) {
        float s = 0.f;
        #pragma unroll 16
        for (int i = 0; i < CC; ++i) s += esv[b * CC + i];
        esum[b] = s;
    }
    __syncthreads();
    {
        float a = esv[tid] / esum[b];
        as_[tid] = a;
        g_a[tid] = a;
    }
    __syncthreads();
    {
        float s = 0.f;
        #pragma unroll 16
        for (int o = 0; o < CC; ++o) s = fmaf(as_[b * CC + o], Wq_s[o * CC + c], s);
        g_weff[tid] = s;
    }
}

// ---------------- K3b: stacked A, ROW-INTERLEAVED, bf16 hi/lo, 64 blocks -----
// M1 row r -> A' row 16*(r>>3) + (r&7); M2 row r -> A' row 16*(r>>3)+8+(r&7).
__global__ void __launch_bounds__(256)
k3b_mats(const float* __restrict__ Wout,
         const float* __restrict__ Wv_spe,
         const float* __restrict__ Wv_spa) {
    const int blk = blockIdx.x;           // 0..63
    const int b = blk >> 3, slice = blk & 7;
    const bool is_m1 = slice < 4;
    const int r0 = (slice & 3) * 16;      // row offset within the 64-row half
    const int tid = threadIdx.x;          // 256
    __shared__ float Wv[CC * CC];
    __shared__ float Wo[16 * CC];
    __shared__ float av[CC];
    const float* wvsrc = is_m1 ? Wv_spa : Wv_spe;
    for (int i = tid; i < CC * CC / 4; i += 256)
        ((float4*)Wv)[i] = ((const float4*)wvsrc)[i];
    if (tid < 16 * CC / 4)
        ((float4*)Wo)[tid] = ((const float4*)(Wout + r0 * CC))[tid];
    if (tid < CC) av[tid] = g_a[b * CC + tid];
    __syncthreads();

    #pragma unroll
    for (int e = tid; e < 512; e += 256) {
        const int rr = e >> 5, cp = e & 31;
        float s0 = 0.f, s1 = 0.f;
        if (is_m1) {
            #pragma unroll 16
            for (int k = 0; k < CC; ++k) {
                const float w = Wo[rr * CC + k];
                s0 = fmaf(w, Wv[k * CC + 2 * cp], s0);
                s1 = fmaf(w, Wv[k * CC + 2 * cp + 1], s1);
            }
        } else {
            #pragma unroll 16
            for (int k = 0; k < CC; ++k) {
                const float w = Wo[rr * CC + k] * av[k];
                s0 = fmaf(w, Wv[k * CC + 2 * cp], s0);
                s1 = fmaf(w, Wv[k * CC + 2 * cp + 1], s1);
            }
        }
        const int r = r0 + rr;                               // row within half
        const int row = 16 * (r >> 3) + (is_m1 ? 0 : 8) + (r & 7);
        float l0, l1;
        const uint32_t hi = bfpack(s0, s1, l0, l1);
        const size_t idx = ((size_t)b * 128 + row) * 32 + cp;
        g_AH[idx] = hi;
        g_AL[idx] = bfpack2(l0, l1);
    }
}

// ---------------- K4: t = w_eff . x per pixel (1024 px/block) ----------------
__global__ void k4_dot(const float* __restrict__ x) {
    const int b = blockIdx.y;
    const int base = blockIdx.x * CHPX1;
    const int tid = threadIdx.x;
    __shared__ float wk[CC];
    if (tid < CC) wk[tid] = g_weff[b * CC + tid];
    __syncthreads();

    float4 a0 = make_float4(0.f, 0.f, 0.f, 0.f);
    #pragma unroll 8
    for (int c = 0; c < CC; ++c) {
        const float w = wk[c];
        const float4 v0 = ((const float4*)(x + ((size_t)b * CC + c) * HWN + base))[tid];
        a0.x = fmaf(w, v0.x, a0.x); a0.y = fmaf(w, v0.y, a0.y);
        a0.z = fmaf(w, v0.z, a0.z); a0.w = fmaf(w, v0.w, a0.w);
    }
    ((float4*)(g_t + (size_t)b * HWN + base))[tid] = a0;
}

// ---------------- K4b: 7x7 conv + sigmoid ------------------------------------
__global__ void k4b_conv(const float* __restrict__ Wnorm) {
    const int b = blockIdx.y;
    const int tid = threadIdx.x;
    const int p = blockIdx.x * 256 + tid;
    __shared__ float wn[49];
    if (tid < 49) wn[tid] = Wnorm[tid];
    __syncthreads();
    const int y = p >> 8;
    const int xx = p & 255;
    const float* tb = g_t + (size_t)b * HWN;
    float acc = 0.f;
    #pragma unroll
    for (int ky = 0; ky < 7; ++ky) {
        const int yy = y + ky - 3;
        const bool yok = (unsigned)yy < 256u;
        #pragma unroll
        for (int kx = 0; kx < 7; ++kx) {
            const int xc = xx + kx - 3;
            float v = (yok && (unsigned)xc < 256u) ? tb[yy * 256 + xc] : 0.f;
            acc = fmaf(wn[ky * 7 + kx], v, acc);
        }
    }
    g_s[(size_t)b * HWN + p] = 1.f / (1.f + expf(-acc));
}

// ---------------- K5: tensor-core final GEMM, ldmatrix + double buffer -------
// X in SMEM pixel-major: row = channel (64 rows x 64 bf16, 144 B stride).
// B fragments via ldmatrix.x4.trans (one x4 = 16k x 16px = two n-tiles).
// Double-buffered X, ONE barrier per subtile. Register epilogue as R13.
__global__ void __launch_bounds__(256)
k5_mma(const float* __restrict__ x, float* __restrict__ out) {
    __shared__ __align__(16) unsigned char XHb[2][CC * XROWB];
    __shared__ __align__(16) unsigned char XLb[2][CC * XROWB];
    __shared__ float ss[256];

    const int b = blockIdx.y;
    const int base0 = blockIdx.x * 256;
    const int tid = threadIdx.x;
    const int lane = tid & 31, w = tid >> 5;
    const int g = lane >> 2, tig = lane & 3;

    // ---- A fragments (hi+lo), loaded once per block -------------------------
    uint32_t ah[4][4], al[4][4];
    {
        const uint32_t* AH = g_AH + (size_t)b * 128 * 32;
        const uint32_t* AL = g_AL + (size_t)b * 128 * 32;
        const int r0 = w * 16 + g;
        #pragma unroll
        for (int k = 0; k < 4; ++k) {
            const int cpb = 8 * k + tig;
            ah[k][0] = __ldg(AH + r0 * 32 + cpb);
            ah[k][1] = __ldg(AH + (r0 + 8) * 32 + cpb);
            ah[k][2] = __ldg(AH + r0 * 32 + cpb + 4);
            ah[k][3] = __ldg(AH + (r0 + 8) * 32 + cpb + 4);
            al[k][0] = __ldg(AL + r0 * 32 + cpb);
            al[k][1] = __ldg(AL + (r0 + 8) * 32 + cpb);
            al[k][2] = __ldg(AL + r0 * 32 + cpb + 4);
            al[k][3] = __ldg(AL + (r0 + 8) * 32 + cpb + 4);
        }
    }
    ss[tid] = g_s[(size_t)b * HWN + base0 + tid];

    const float* xb = x + (size_t)b * CC * HWN;
    // per-thread load slots: channel-pair cp, pixel group px (4 px)
    const int cp0 = tid >> 4, px0 = (tid & 15) * 4;
    const int cp1 = cp0 + 16;

    // prefetch subtile 0 (each float4 = 4 px of ONE channel)
    float4 p0a = __ldg((const float4*)(xb + (size_t)(2 * cp0) * HWN + base0 + px0));
    float4 p0b = __ldg((const float4*)(xb + (size_t)(2 * cp0 + 1) * HWN + base0 + px0));
    float4 p1a = __ldg((const float4*)(xb + (size_t)(2 * cp1) * HWN + base0 + px0));
    float4 p1b = __ldg((const float4*)(xb + (size_t)(2 * cp1 + 1) * HWN + base0 + px0));

    // ldmatrix per-thread byte offset: row = lane&15, col block +8px for lane>=16
    const int lmoff = (lane & 15) * XROWB + ((lane & 16) ? 16 : 0);

    for (int st = 0; st < 4; ++st) {
        const int base = base0 + st * 64;
        const int buf = st & 1;

        // ---- convert prefetched regs -> pixel-major bf16 hi/lo --------------
        #pragma unroll
        for (int h = 0; h < 2; ++h) {
            const float4 va = h ? p1a : p0a;     // 4 px of channel 2cp
            const float4 vb = h ? p1b : p0b;     // 4 px of channel 2cp+1
            const int cp = h ? cp1 : cp0;
            unsigned char* rh0 = XHb[buf] + (2 * cp) * XROWB + px0 * 2;
            unsigned char* rh1 = XHb[buf] + (2 * cp + 1) * XROWB + px0 * 2;
            unsigned char* rl0 = XLb[buf] + (2 * cp) * XROWB + px0 * 2;
            unsigned char* rl1 = XLb[buf] + (2 * cp + 1) * XROWB + px0 * 2;
            uint2 hh0, hh1, ll0, ll1;
            hh0.x = prmt_hi(__float_as_uint(va.x), __float_as_uint(va.y));
            hh0.y = prmt_hi(__float_as_uint(va.z), __float_as_uint(va.w));
            hh1.x = prmt_hi(__float_as_uint(vb.x), __float_as_uint(vb.y));
            hh1.y = prmt_hi(__float_as_uint(vb.z), __float_as_uint(vb.w));
            ll0.x = cvt_bf16x2(trunc_resid(va.y), trunc_resid(va.x));
            ll0.y = cvt_bf16x2(trunc_resid(va.w), trunc_resid(va.z));
            ll1.x = cvt_bf16x2(trunc_resid(vb.y), trunc_resid(vb.x));
            ll1.y = cvt_bf16x2(trunc_resid(vb.w), trunc_resid(vb.z));
            *(uint2*)rh0 = hh0;
            *(uint2*)rh1 = hh1;
            *(uint2*)rl0 = ll0;
            *(uint2*)rl1 = ll1;
        }
        __syncthreads();   // single barrier per subtile (safe with 2 buffers)

        // ---- prefetch next subtile (overlaps with mma below) ----------------
        if (st < 3) {
            const int nb = base + 64;
            p0a = __ldg((const float4*)(xb + (size_t)(2 * cp0) * HWN + nb + px0));
            p0b = __ldg((const float4*)(xb + (size_t)(2 * cp0 + 1) * HWN + nb + px0));
            p1a = __ldg((const float4*)(xb + (size_t)(2 * cp1) * HWN + nb + px0));
            p1b = __ldg((const float4*)(xb + (size_t)(2 * cp1 + 1) * HWN + nb + px0));
        }

        // ---- mma: ldmatrix B loads, accumulate d[8][4] over k ---------------
        const uint32_t hbase =
            (uint32_t)__cvta_generic_to_shared(XHb[buf]) + lmoff;
        const uint32_t lbase =
            (uint32_t)__cvta_generic_to_shared(XLb[buf]) + lmoff;

        float d[8][4];
        #pragma unroll
        for (int n = 0; n < 8; ++n)
            #pragma unroll
            for (int j = 0; j < 4; ++j) d[n][j] = 0.f;

        #pragma unroll
        for (int k = 0; k < 4; ++k) {
            #pragma unroll
            for (int ng = 0; ng < 4; ++ng) {
                const uint32_t off = k * (16 * XROWB) + ng * 32;
                uint32_t h0, h1, h2, h3, l0, l1, l2, l3;
                ldsm_x4_trans(h0, h1, h2, h3, hbase + off);
                ldsm_x4_trans(l0, l1, l2, l3, lbase + off);
                MMA16816(d[2 * ng][0], d[2 * ng][1], d[2 * ng][2], d[2 * ng][3],
                         ah[k][0], ah[k][1], ah[k][2], ah[k][3], h0, h1);
                MMA16816(d[2 * ng][0], d[2 * ng][1], d[2 * ng][2], d[2 * ng][3],
                         ah[k][0], ah[k][1], ah[k][2], ah[k][3], l0, l1);
                MMA16816(d[2 * ng][0], d[2 * ng][1], d[2 * ng][2], d[2 * ng][3],
                         al[k][0], al[k][1], al[k][2], al[k][3], h0, h1);
                MMA16816(d[2 * ng + 1][0], d[2 * ng + 1][1], d[2 * ng + 1][2], d[2 * ng + 1][3],
                         ah[k][0], ah[k][1], ah[k][2], ah[k][3], h2, h3);
                MMA16816(d[2 * ng + 1][0], d[2 * ng + 1][1], d[2 * ng + 1][2], d[2 * ng + 1][3],
                         ah[k][0], ah[k][1], ah[k][2], ah[k][3], l2, l3);
                MMA16816(d[2 * ng + 1][0], d[2 * ng + 1][1], d[2 * ng + 1][2], d[2 * ng + 1][3],
                         al[k][0], al[k][1], al[k][2], al[k][3], h2, h3);
            }
        }

        // ---- register epilogue: out = y2 + s*y1 -----------------------------
        const int orow = 8 * w + g;
        float* orp = out + ((size_t)b * CC + orow) * HWN + base;
        const float* sb = ss + st * 64;
        #pragma unroll
        for (int n = 0; n < 8; ++n) {
            const int col = 8 * n + 2 * tig;
            const float2 sv = *(const float2*)(sb + col);
            float2 o2;
            o2.x = fmaf(sv.x, d[n][0], d[n][2]);
            o2.y = fmaf(sv.y, d[n][1], d[n][3]);
            *(float2*)(orp + col) = o2;
        }
    }
}

// ---------------- launch ------------------------------------------------------
extern "C" void kernel_launch(void* const* d_in, const int* in_sizes, int n_in,
                              void* d_out, int out_size) {
    const float* x      = (const float*)d_in[0];
    const float* Wq     = (const float*)d_in[1];
    const float* Wk     = (const float*)d_in[2];
    const float* Wv_spe = (const float*)d_in[3];
    const float* Wv_spa = (const float*)d_in[4];
    const float* Wup    = (const float*)d_in[5];
    const float* Wout   = (const float*)d_in[6];
    const float* Wnorm  = (const float*)d_in[7];
    float* out = (float*)d_out;

    static int attr_set = 0;
    if (!attr_set) {
        cudaFuncSetAttribute(k12_fused,
                             cudaFuncAttributeMaxDynamicSharedMemorySize, K12_SMEM);
        attr_set = 1;
    }

    k12_fused<<<dim3(NCHK, BB), 256, K12_SMEM>>>(x, Wk);
    k3_stats<<<1, 512>>>(Wq, Wup);
    k3b_mats<<<64, 256>>>(Wout, Wv_spe, Wv_spa);
    k4_dot<<<dim3(NCHK, BB), 256>>>(x);
    k4b_conv<<<dim3(HWN / 256, BB), 256>>>(Wnorm);
    k5_mma<<<dim3(HWN / 256, BB), 256>>>(x, out);
}

// round 15
// speedup vs baseline: 1.0682x; 1.0682x over previous
#include <cuda_runtime.h>
#include <cuda_bf16.h>
#include <cstdint>
#include <math.h>

// Problem constants
#define BB 8
#define CC 64
#define HWN 65536
#define NCHK 64                // chunks (1024 px each) for k12/k4
#define CHPX1 1024
#define SUBPX 256              // k12 smem subtile width

typedef unsigned long long ull;

// ---- k12 smem layout (floats) ----
#define K12_XS    0                     // 64*256 = 16384 floats
#define K12_ES    16384                 // 256
#define K12_RED   16640                 // 8
#define K12_SMEM  (16648 * 4)           // bytes

// ---- k5: X tile row stride (u32 words). 72%32==8 -> conflict-free B reads ----
#define XST      72

// ---------------- scratch (device globals) -----------------------------------
__device__ float g_t[BB * HWN];           // pre-conv spatial attention
__device__ float g_s[BB * HWN];           // sigmoid(conv(t))
__device__ float g_Zpart[BB * NCHK];
__device__ float g_pooledpart[BB * NCHK * CC];
__device__ float g_weff[BB * CC];         // a^T Wq
// Row-interleaved stacked A: tile w rows [16w,16w+8) = M1[8w..8w+8),
// rows [16w+8,16w+16) = M2[8w..8w+8). bf16x2 pair-packed over input channel.
__device__ uint32_t g_AH[BB * 128 * 32];  // hi part
__device__ uint32_t g_AL[BB * 128 * 32];  // lo part

// ---------------- mma.sync m16n8k16 bf16 -------------------------------------
#define MMA16816(d0, d1, d2, d3, a0, a1, a2, a3, b0, b1)                     \
    asm volatile(                                                            \
        "mma.sync.aligned.m16n8k16.row.col.f32.bf16.bf16.f32 "               \
        "{%0,%1,%2,%3}, {%4,%5,%6,%7}, {%8,%9}, {%0,%1,%2,%3};"              \
        : "+f"(d0), "+f"(d1), "+f"(d2), "+f"(d3)                             \
        : "r"(a0), "r"(a1), "r"(a2), "r"(a3), "r"(b0), "r"(b1))

__device__ __forceinline__ uint32_t bfpack(float v0, float v1,
                                           float& l0, float& l1) {
    __nv_bfloat16 h0 = __float2bfloat16_rn(v0);
    __nv_bfloat16 h1 = __float2bfloat16_rn(v1);
    l0 = v0 - __bfloat162float(h0);
    l1 = v1 - __bfloat162float(h1);
    return (uint32_t)__bfloat16_as_ushort(h0) |
           ((uint32_t)__bfloat16_as_ushort(h1) << 16);
}
__device__ __forceinline__ uint32_t bfpack2(float v0, float v1) {
    return (uint32_t)__bfloat16_as_ushort(__float2bfloat16_rn(v0)) |
           ((uint32_t)__bfloat16_as_ushort(__float2bfloat16_rn(v1)) << 16);
}
// Truncation split: hi = top-16-bits of each fp32 (exact bf16), packed by PRMT.
__device__ __forceinline__ uint32_t prmt_hi(uint32_t u0, uint32_t u1) {
    uint32_t r;
    asm("prmt.b32 %0, %1, %2, 0x7632;" : "=r"(r) : "r"(u0), "r"(u1));
    return r;
}
// d = { lo half = bf16(lo), hi half = bf16(hi) }
__device__ __forceinline__ uint32_t cvt_bf16x2(float hi, float lo) {
    uint32_t r;
    asm("cvt.rn.bf16x2.f32 %0, %1, %2;" : "=r"(r) : "f"(hi), "f"(lo));
    return r;
}

// ---------------- K12: fused exp(k logits) + weighted pooling ----------------
__global__ void __launch_bounds__(256)
k12_fused(const float* __restrict__ x, const float* __restrict__ Wk) {
    extern __shared__ float sh[];
    float* xs  = sh + K12_XS;
    float* es  = sh + K12_ES;
    float* red = sh + K12_RED;
    __shared__ float wk[CC];

    const int b = blockIdx.y;
    const int chunk = blockIdx.x;
    const int base = chunk * CHPX1;
    const int tid = threadIdx.x;
    const int wid = tid >> 5, lid = tid & 31;
    if (tid < CC) wk[tid] = Wk[tid];

    const float* xb = x + (size_t)b * CC * HWN;
    float zacc = 0.f;
    float pacc[8];
    #pragma unroll
    for (int j = 0; j < 8; ++j) pacc[j] = 0.f;

    for (int s = 0; s < 4; ++s) {
        const int pbase = base + s * SUBPX;
        __syncthreads();
        #pragma unroll
        for (int i = tid; i < 4096; i += 256) {
            const int c = i >> 6, k = i & 63;
            ((float4*)(xs + c * SUBPX))[k] =
                __ldg((const float4*)(xb + (size_t)c * HWN + pbase) + k);
        }
        __syncthreads();
        float lg = 0.f;
        #pragma unroll 16
        for (int c = 0; c < CC; ++c)
            lg = fmaf(wk[c], xs[c * SUBPX + tid], lg);
        const float e = expf(lg);
        es[tid] = e;
        zacc += e;
        __syncthreads();
        #pragma unroll
        for (int j = 0; j < 8; ++j) {
            const int c = wid * 8 + j;
            const float4* xr = (const float4*)(xs + c * SUBPX);
            const float4* er = (const float4*)es;
            float a = 0.f;
            #pragma unroll
            for (int q = 0; q < 2; ++q) {
                const float4 v = xr[lid * 2 + q];
                const float4 e4 = er[lid * 2 + q];
                a += v.x * e4.x + v.y * e4.y + v.z * e4.z + v.w * e4.w;
            }
            pacc[j] += a;
        }
    }

    #pragma unroll
    for (int j = 0; j < 8; ++j) {
        #pragma unroll
        for (int off = 16; off; off >>= 1)
            pacc[j] += __shfl_xor_sync(0xffffffffu, pacc[j], off);
    }
    if (lid == 0) {
        #pragma unroll
        for (int j = 0; j < 8; ++j)
            g_pooledpart[((size_t)b * NCHK + chunk) * CC + wid * 8 + j] = pacc[j];
    }
    #pragma unroll
    for (int off = 16; off; off >>= 1)
        zacc += __shfl_xor_sync(0xffffffffu, zacc, off);
    if (lid == 0) red[wid] = zacc;
    __syncthreads();
    if (tid == 0) {
        float zz = 0.f;
        #pragma unroll
        for (int w = 0; w < 8; ++w) zz += red[w];
        g_Zpart[b * NCHK + chunk] = zz;
    }
}

// ---------------- K3B: fused channel-attention chain + stacked A build -------
// 64 blocks: (b, slice). Each block recomputes the per-batch attention chain
// (pooled -> att -> uu -> softmax a) for ITS batch (bit-identical across the
// 8 blocks of a batch), then builds its 16-row slice of the row-interleaved
// stacked A = [M1;M2[b]] in bf16 hi/lo. slice==0 blocks also write g_weff[b].
// M1 row r -> A' row 16*(r>>3) + (r&7); M2 row r -> A' row 16*(r>>3)+8+(r&7).
__global__ void __launch_bounds__(256)
k3b_fused(const float* __restrict__ Wq, const float* __restrict__ Wup,
          const float* __restrict__ Wout,
          const float* __restrict__ Wv_spe, const float* __restrict__ Wv_spa) {
    const int blk = blockIdx.x;           // 0..63
    const int b = blk >> 3, slice = blk & 7;
    const bool is_m1 = slice < 4;
    const int r0 = (slice & 3) * 16;      // row offset within the 64-row half
    const int tid = threadIdx.x;          // 256

    __shared__ float Wq_s[CC * CC];       // 16 KB (chain + weff)
    __shared__ float Wv[CC * CC];         // 16 KB
    __shared__ float Wo[16 * CC];         // 4 KB
    __shared__ float pooled[CC];
    __shared__ float att[CC];
    __shared__ float uu[CC];
    __shared__ float av[CC];
    __shared__ float zsh;

    const float* wvsrc = is_m1 ? Wv_spa : Wv_spe;
    for (int i = tid; i < CC * CC / 4; i += 256) {
        ((float4*)Wq_s)[i] = ((const float4*)Wq)[i];
        ((float4*)Wv)[i]   = ((const float4*)wvsrc)[i];
    }
    if (tid < 16 * CC / 4)
        ((float4*)Wo)[tid] = ((const float4*)(Wout + r0 * CC))[tid];

    // ---- per-batch chain (threads 0..63) ------------------------------------
    if (tid < CC) {
        float s = 0.f;
        #pragma unroll 16
        for (int ch = 0; ch < NCHK; ++ch)
            s += g_pooledpart[((size_t)b * NCHK + ch) * CC + tid];
        pooled[tid] = s;
    }
    if (tid == 0) {
        float z = 0.f;
        #pragma unroll 16
        for (int ch = 0; ch < NCHK; ++ch) z += g_Zpart[b * NCHK + ch];
        zsh = z;
    }
    __syncthreads();
    if (tid < CC) {
        const float inv = 1.f / zsh;
        float s = 0.f;
        #pragma unroll 16
        for (int i = 0; i < CC; ++i)
            s = fmaf(Wq_s[tid * CC + i], pooled[i], s);
        att[tid] = s * inv;
    }
    __syncthreads();
    if (tid < CC) {
        float s = 0.f;
        #pragma unroll 16
        for (int i = 0; i < CC; ++i)
            s = fmaf(__ldg(Wup + tid * CC + i), att[i], s);
        uu[tid] = s;
    }
    __syncthreads();
    if (tid < CC) {
        float m = -3.4e38f;
        #pragma unroll 16
        for (int i = 0; i < CC; ++i) m = fmaxf(m, uu[i]);
        float sum = 0.f;
        #pragma unroll 8
        for (int i = 0; i < CC; ++i) sum += expf(uu[i] - m);
        av[tid] = expf(uu[tid] - m) / sum;
    }
    __syncthreads();
    if (is_m1 && (slice == 0) && tid < CC) {   // w_eff for k4 (one block/batch)
        float s = 0.f;
        #pragma unroll 16
        for (int o = 0; o < CC; ++o)
            s = fmaf(av[o], Wq_s[o * CC + tid], s);
        g_weff[b * CC + tid] = s;
    }

    // ---- build this block's 16-row A slice ----------------------------------
    #pragma unroll
    for (int e = tid; e < 512; e += 256) {
        const int rr = e >> 5, cp = e & 31;
        float s0 = 0.f, s1 = 0.f;
        if (is_m1) {
            #pragma unroll 16
            for (int k = 0; k < CC; ++k) {
                const float w = Wo[rr * CC + k];
                s0 = fmaf(w, Wv[k * CC + 2 * cp], s0);
                s1 = fmaf(w, Wv[k * CC + 2 * cp + 1], s1);
            }
        } else {
            #pragma unroll 16
            for (int k = 0; k < CC; ++k) {
                const float w = Wo[rr * CC + k] * av[k];
                s0 = fmaf(w, Wv[k * CC + 2 * cp], s0);
                s1 = fmaf(w, Wv[k * CC + 2 * cp + 1], s1);
            }
        }
        const int r = r0 + rr;                               // row within half
        const int row = 16 * (r >> 3) + (is_m1 ? 0 : 8) + (r & 7);
        float l0, l1;
        const uint32_t hi = bfpack(s0, s1, l0, l1);
        const size_t idx = ((size_t)b * 128 + row) * 32 + cp;
        g_AH[idx] = hi;
        g_AL[idx] = bfpack2(l0, l1);
    }
}

// ---------------- K4: t = w_eff . x per pixel (1024 px/block) ----------------
__global__ void k4_dot(const float* __restrict__ x) {
    const int b = blockIdx.y;
    const int base = blockIdx.x * CHPX1;
    const int tid = threadIdx.x;
    __shared__ float wk[CC];
    if (tid < CC) wk[tid] = g_weff[b * CC + tid];
    __syncthreads();

    float4 a0 = make_float4(0.f, 0.f, 0.f, 0.f);
    #pragma unroll 8
    for (int c = 0; c < CC; ++c) {
        const float w = wk[c];
        const float4 v0 = ((const float4*)(x + ((size_t)b * CC + c) * HWN + base))[tid];
        a0.x = fmaf(w, v0.x, a0.x); a0.y = fmaf(w, v0.y, a0.y);
        a0.z = fmaf(w, v0.z, a0.z); a0.w = fmaf(w, v0.w, a0.w);
    }
    ((float4*)(g_t + (size_t)b * HWN + base))[tid] = a0;
}

// ---------------- K4b: 7x7 conv + sigmoid ------------------------------------
__global__ void k4b_conv(const float* __restrict__ Wnorm) {
    const int b = blockIdx.y;
    const int tid = threadIdx.x;
    const int p = blockIdx.x * 256 + tid;
    __shared__ float wn[49];
    if (tid < 49) wn[tid] = Wnorm[tid];
    __syncthreads();
    const int y = p >> 8;
    const int xx = p & 255;
    const float* tb = g_t + (size_t)b * HWN;
    float acc = 0.f;
    #pragma unroll
    for (int ky = 0; ky < 7; ++ky) {
        const int yy = y + ky - 3;
        const bool yok = (unsigned)yy < 256u;
        #pragma unroll
        for (int kx = 0; kx < 7; ++kx) {
            const int xc = xx + kx - 3;
            float v = (yok && (unsigned)xc < 256u) ? tb[yy * 256 + xc] : 0.f;
            acc = fmaf(wn[ky * 7 + kx], v, acc);
        }
    }
    g_s[(size_t)b * HWN + p] = 1.f / (1.f + expf(-acc));
}

// ---------------- K5: tensor-core final GEMM, register epilogue (R13) --------
// A row-interleaved: warp w tile = {M1[8w..8w+8); M2[8w..8w+8)} so a thread's
// d0/d1 (y1) and d2/d3 (y2) share the output row: out = fmaf(s, y1, y2).
__global__ void __launch_bounds__(256)
k5_mma(const float* __restrict__ x, float* __restrict__ out) {
    __shared__ uint32_t XH[32 * XST];
    __shared__ uint32_t XL[32 * XST];
    __shared__ float ss[256];

    const int b = blockIdx.y;
    const int base0 = blockIdx.x * 256;
    const int tid = threadIdx.x;
    const int lane = tid & 31, w = tid >> 5;
    const int g = lane >> 2, tig = lane & 3;

    // ---- A fragments (hi+lo), loaded once per block -------------------------
    uint32_t ah[4][4], al[4][4];
    {
        const uint32_t* AH = g_AH + (size_t)b * 128 * 32;
        const uint32_t* AL = g_AL + (size_t)b * 128 * 32;
        const int r0 = w * 16 + g;
        #pragma unroll
        for (int k = 0; k < 4; ++k) {
            const int cpb = 8 * k + tig;
            ah[k][0] = __ldg(AH + r0 * 32 + cpb);
            ah[k][1] = __ldg(AH + (r0 + 8) * 32 + cpb);
            ah[k][2] = __ldg(AH + r0 * 32 + cpb + 4);
            ah[k][3] = __ldg(AH + (r0 + 8) * 32 + cpb + 4);
            al[k][0] = __ldg(AL + r0 * 32 + cpb);
            al[k][1] = __ldg(AL + (r0 + 8) * 32 + cpb);
            al[k][2] = __ldg(AL + r0 * 32 + cpb + 4);
            al[k][3] = __ldg(AL + (r0 + 8) * 32 + cpb + 4);
        }
    }
    ss[tid] = g_s[(size_t)b * HWN + base0 + tid];

    const float* xb = x + (size_t)b * CC * HWN;
    const int cp0 = tid >> 4,         px0 = (tid & 15) * 4;
    const int cp1 = (tid + 256) >> 4, px1 = (tid & 15) * 4;

    float4 p0a = __ldg((const float4*)(xb + (size_t)(2 * cp0) * HWN + base0 + px0));
    float4 p0b = __ldg((const float4*)(xb + (size_t)(2 * cp0 + 1) * HWN + base0 + px0));
    float4 p1a = __ldg((const float4*)(xb + (size_t)(2 * cp1) * HWN + base0 + px1));
    float4 p1b = __ldg((const float4*)(xb + (size_t)(2 * cp1 + 1) * HWN + base0 + px1));

    for (int st = 0; st < 4; ++st) {
        const int base = base0 + st * 64;

        // ---- convert prefetched regs -> XH/XL (truncation split) ------------
        {
            #pragma unroll
            for (int h = 0; h < 2; ++h) {
                const float4 va = h ? p1a : p0a;
                const float4 vb = h ? p1b : p0b;
                const int cp = h ? cp1 : cp0;
                const int px = h ? px1 : px0;
                const float a0 = va.x, a1 = va.y, a2 = va.z, a3 = va.w;
                const float b0 = vb.x, b1 = vb.y, b2 = vb.z, b3 = vb.w;
                uint4 hh, ll;
                hh.x = prmt_hi(__float_as_uint(a0), __float_as_uint(b0));
                hh.y = prmt_hi(__float_as_uint(a1), __float_as_uint(b1));
                hh.z = prmt_hi(__float_as_uint(a2), __float_as_uint(b2));
                hh.w = prmt_hi(__float_as_uint(a3), __float_as_uint(b3));
                ll.x = cvt_bf16x2(b0 - __uint_as_float(__float_as_uint(b0) & 0xFFFF0000u),
                                  a0 - __uint_as_float(__float_as_uint(a0) & 0xFFFF0000u));
                ll.y = cvt_bf16x2(b1 - __uint_as_float(__float_as_uint(b1) & 0xFFFF0000u),
                                  a1 - __uint_as_float(__float_as_uint(a1) & 0xFFFF0000u));
                ll.z = cvt_bf16x2(b2 - __uint_as_float(__float_as_uint(b2) & 0xFFFF0000u),
                                  a2 - __uint_as_float(__float_as_uint(a2) & 0xFFFF0000u));
                ll.w = cvt_bf16x2(b3 - __uint_as_float(__float_as_uint(b3) & 0xFFFF0000u),
                                  a3 - __uint_as_float(__float_as_uint(a3) & 0xFFFF0000u));
                *(uint4*)(XH + cp * XST + px) = hh;
                *(uint4*)(XL + cp * XST + px) = ll;
            }
        }
        __syncthreads();

        // ---- prefetch next subtile (overlaps with mma below) ----------------
        if (st < 3) {
            const int nb = base + 64;
            p0a = __ldg((const float4*)(xb + (size_t)(2 * cp0) * HWN + nb + px0));
            p0b = __ldg((const float4*)(xb + (size_t)(2 * cp0 + 1) * HWN + nb + px0));
            p1a = __ldg((const float4*)(xb + (size_t)(2 * cp1) * HWN + nb + px1));
            p1b = __ldg((const float4*)(xb + (size_t)(2 * cp1 + 1) * HWN + nb + px1));
        }

        // ---- mma + register epilogue ----------------------------------------
        const int orow = 8 * w + g;
        float* orp = out + ((size_t)b * CC + orow) * HWN + base;
        const float* sb = ss + st * 64;
        #pragma unroll
        for (int n = 0; n < 8; ++n) {
            float d0 = 0.f, d1 = 0.f, d2 = 0.f, d3 = 0.f;
            const int pxg = 8 * n + g;
            #pragma unroll
            for (int k = 0; k < 4; ++k) {
                const uint32_t bh0 = XH[(8 * k + tig) * XST + pxg];
                const uint32_t bh1 = XH[(8 * k + tig + 4) * XST + pxg];
                const uint32_t bl0 = XL[(8 * k + tig) * XST + pxg];
                const uint32_t bl1 = XL[(8 * k + tig + 4) * XST + pxg];
                MMA16816(d0, d1, d2, d3, ah[k][0], ah[k][1], ah[k][2], ah[k][3], bh0, bh1);
                MMA16816(d0, d1, d2, d3, ah[k][0], ah[k][1], ah[k][2], ah[k][3], bl0, bl1);
                MMA16816(d0, d1, d2, d3, al[k][0], al[k][1], al[k][2], al[k][3], bh0, bh1);
            }
            const int col = 8 * n + 2 * tig;
            const float2 sv = *(const float2*)(sb + col);
            float2 o2;
            o2.x = fmaf(sv.x, d0, d2);
            o2.y = fmaf(sv.y, d1, d3);
            *(float2*)(orp + col) = o2;
        }
        __syncthreads();   // protect XH/XL before next overwrite
    }
}

// ---------------- launch ------------------------------------------------------
extern "C" void kernel_launch(void* const* d_in, const int* in_sizes, int n_in,
                              void* d_out, int out_size) {
    const float* x      = (const float*)d_in[0];
    const float* Wq     = (const float*)d_in[1];
    const float* Wk     = (const float*)d_in[2];
    const float* Wv_spe = (const float*)d_in[3];
    const float* Wv_spa = (const float*)d_in[4];
    const float* Wup    = (const float*)d_in[5];
    const float* Wout   = (const float*)d_in[6];
    const float* Wnorm  = (const float*)d_in[7];
    float* out = (float*)d_out;

    static int attr_set = 0;
    if (!attr_set) {
        cudaFuncSetAttribute(k12_fused,
                             cudaFuncAttributeMaxDynamicSharedMemorySize, K12_SMEM);
        attr_set = 1;
    }

    k12_fused<<<dim3(NCHK, BB), 256, K12_SMEM>>>(x, Wk);
    k3b_fused<<<64, 256>>>(Wq, Wup, Wout, Wv_spe, Wv_spa);
    k4_dot<<<dim3(NCHK, BB), 256>>>(x);
    k4b_conv<<<dim3(HWN / 256, BB), 256>>>(Wnorm);
    k5_mma<<<dim3(HWN / 256, BB), 256>>>(x, out);
}

// round 16
// speedup vs baseline: 1.0814x; 1.0123x over previous
#include <cuda_runtime.h>
#include <cuda_bf16.h>
#include <cstdint>
#include <math.h>

// Problem constants
#define BB 8
#define CC 64
#define HWN 65536
#define NCHK 64                // chunks (1024 px each) for k12/k4
#define CHPX1 1024
#define SUBPX 256              // k12 smem subtile width

typedef unsigned long long ull;

// ---- k12 smem layout (floats) ----
#define K12_XS    0                     // 64*256 = 16384 floats
#define K12_ES    16384                 // 256
#define K12_RED   16640                 // 8
#define K12_SMEM  (16648 * 4)           // bytes

// ---- k5: X tile row stride (u32 words). 72%32==8 -> conflict-free B reads ----
#define XST      72

// ---- k4b conv tiling: 64x16 outputs, 3-px halo ----
#define CTW      64
#define CTH      16
#define CHW      70            // CTW + 6
#define CHH      22            // CTH + 6
#define CST      72            // padded smem row stride (floats)

// ---------------- scratch (device globals) -----------------------------------
__device__ float g_t[BB * HWN];           // pre-conv spatial attention
__device__ float g_s[BB * HWN];           // sigmoid(conv(t))
__device__ float g_Zpart[BB * NCHK];
__device__ float g_pooledpart[BB * NCHK * CC];
__device__ float g_weff[BB * CC];         // a^T Wq
// Row-interleaved stacked A: tile w rows [16w,16w+8) = M1[8w..8w+8),
// rows [16w+8,16w+16) = M2[8w..8w+8). bf16x2 pair-packed over input channel.
__device__ uint32_t g_AH[BB * 128 * 32];  // hi part
__device__ uint32_t g_AL[BB * 128 * 32];  // lo part

// ---------------- mma.sync m16n8k16 bf16 -------------------------------------
#define MMA16816(d0, d1, d2, d3, a0, a1, a2, a3, b0, b1)                     \
    asm volatile(                                                            \
        "mma.sync.aligned.m16n8k16.row.col.f32.bf16.bf16.f32 "               \
        "{%0,%1,%2,%3}, {%4,%5,%6,%7}, {%8,%9}, {%0,%1,%2,%3};"              \
        : "+f"(d0), "+f"(d1), "+f"(d2), "+f"(d3)                             \
        : "r"(a0), "r"(a1), "r"(a2), "r"(a3), "r"(b0), "r"(b1))

__device__ __forceinline__ uint32_t bfpack(float v0, float v1,
                                           float& l0, float& l1) {
    __nv_bfloat16 h0 = __float2bfloat16_rn(v0);
    __nv_bfloat16 h1 = __float2bfloat16_rn(v1);
    l0 = v0 - __bfloat162float(h0);
    l1 = v1 - __bfloat162float(h1);
    return (uint32_t)__bfloat16_as_ushort(h0) |
           ((uint32_t)__bfloat16_as_ushort(h1) << 16);
}
__device__ __forceinline__ uint32_t bfpack2(float v0, float v1) {
    return (uint32_t)__bfloat16_as_ushort(__float2bfloat16_rn(v0)) |
           ((uint32_t)__bfloat16_as_ushort(__float2bfloat16_rn(v1)) << 16);
}
// Truncation split: hi = top-16-bits of each fp32 (exact bf16), packed by PRMT.
__device__ __forceinline__ uint32_t prmt_hi(uint32_t u0, uint32_t u1) {
    uint32_t r;
    asm("prmt.b32 %0, %1, %2, 0x7632;" : "=r"(r) : "r"(u0), "r"(u1));
    return r;
}
// d = { lo half = bf16(lo), hi half = bf16(hi) }
__device__ __forceinline__ uint32_t cvt_bf16x2(float hi, float lo) {
    uint32_t r;
    asm("cvt.rn.bf16x2.f32 %0, %1, %2;" : "=r"(r) : "f"(hi), "f"(lo));
    return r;
}

// ---------------- K12: fused exp(k logits) + weighted pooling ----------------
__global__ void __launch_bounds__(256)
k12_fused(const float* __restrict__ x, const float* __restrict__ Wk) {
    extern __shared__ float sh[];
    float* xs  = sh + K12_XS;
    float* es  = sh + K12_ES;
    float* red = sh + K12_RED;
    __shared__ float wk[CC];

    const int b = blockIdx.y;
    const int chunk = blockIdx.x;
    const int base = chunk * CHPX1;
    const int tid = threadIdx.x;
    const int wid = tid >> 5, lid = tid & 31;
    if (tid < CC) wk[tid] = Wk[tid];

    const float* xb = x + (size_t)b * CC * HWN;
    float zacc = 0.f;
    float pacc[8];
    #pragma unroll
    for (int j = 0; j < 8; ++j) pacc[j] = 0.f;

    for (int s = 0; s < 4; ++s) {
        const int pbase = base + s * SUBPX;
        __syncthreads();
        #pragma unroll
        for (int i = tid; i < 4096; i += 256) {
            const int c = i >> 6, k = i & 63;
            ((float4*)(xs + c * SUBPX))[k] =
                __ldg((const float4*)(xb + (size_t)c * HWN + pbase) + k);
        }
        __syncthreads();
        float lg = 0.f;
        #pragma unroll 16
        for (int c = 0; c < CC; ++c)
            lg = fmaf(wk[c], xs[c * SUBPX + tid], lg);
        const float e = expf(lg);
        es[tid] = e;
        zacc += e;
        __syncthreads();
        #pragma unroll
        for (int j = 0; j < 8; ++j) {
            const int c = wid * 8 + j;
            const float4* xr = (const float4*)(xs + c * SUBPX);
            const float4* er = (const float4*)es;
            float a = 0.f;
            #pragma unroll
            for (int q = 0; q < 2; ++q) {
                const float4 v = xr[lid * 2 + q];
                const float4 e4 = er[lid * 2 + q];
                a += v.x * e4.x + v.y * e4.y + v.z * e4.z + v.w * e4.w;
            }
            pacc[j] += a;
        }
    }

    #pragma unroll
    for (int j = 0; j < 8; ++j) {
        #pragma unroll
        for (int off = 16; off; off >>= 1)
            pacc[j] += __shfl_xor_sync(0xffffffffu, pacc[j], off);
    }
    if (lid == 0) {
        #pragma unroll
        for (int j = 0; j < 8; ++j)
            g_pooledpart[((size_t)b * NCHK + chunk) * CC + wid * 8 + j] = pacc[j];
    }
    #pragma unroll
    for (int off = 16; off; off >>= 1)
        zacc += __shfl_xor_sync(0xffffffffu, zacc, off);
    if (lid == 0) red[wid] = zacc;
    __syncthreads();
    if (tid == 0) {
        float zz = 0.f;
        #pragma unroll
        for (int w = 0; w < 8; ++w) zz += red[w];
        g_Zpart[b * NCHK + chunk] = zz;
    }
}

// ---------------- K3B: fused channel-attention chain + stacked A build -------
// 64 blocks: (b, slice). Each block recomputes the per-batch attention chain
// for ITS batch, then builds its 16-row slice of row-interleaved A=[M1;M2[b]].
__global__ void __launch_bounds__(256)
k3b_fused(const float* __restrict__ Wq, const float* __restrict__ Wup,
          const float* __restrict__ Wout,
          const float* __restrict__ Wv_spe, const float* __restrict__ Wv_spa) {
    const int blk = blockIdx.x;           // 0..63
    const int b = blk >> 3, slice = blk & 7;
    const bool is_m1 = slice < 4;
    const int r0 = (slice & 3) * 16;      // row offset within the 64-row half
    const int tid = threadIdx.x;          // 256

    __shared__ float Wq_s[CC * CC];
    __shared__ float Wv[CC * CC];
    __shared__ float Wo[16 * CC];
    __shared__ float pooled[CC];
    __shared__ float att[CC];
    __shared__ float uu[CC];
    __shared__ float av[CC];
    __shared__ float zsh;

    const float* wvsrc = is_m1 ? Wv_spa : Wv_spe;
    for (int i = tid; i < CC * CC / 4; i += 256) {
        ((float4*)Wq_s)[i] = ((const float4*)Wq)[i];
        ((float4*)Wv)[i]   = ((const float4*)wvsrc)[i];
    }
    if (tid < 16 * CC / 4)
        ((float4*)Wo)[tid] = ((const float4*)(Wout + r0 * CC))[tid];

    if (tid < CC) {
        float s = 0.f;
        #pragma unroll 16
        for (int ch = 0; ch < NCHK; ++ch)
            s += g_pooledpart[((size_t)b * NCHK + ch) * CC + tid];
        pooled[tid] = s;
    }
    if (tid == 0) {
        float z = 0.f;
        #pragma unroll 16
        for (int ch = 0; ch < NCHK; ++ch) z += g_Zpart[b * NCHK + ch];
        zsh = z;
    }
    __syncthreads();
    if (tid < CC) {
        const float inv = 1.f / zsh;
        float s = 0.f;
        #pragma unroll 16
        for (int i = 0; i < CC; ++i)
            s = fmaf(Wq_s[tid * CC + i], pooled[i], s);
        att[tid] = s * inv;
    }
    __syncthreads();
    if (tid < CC) {
        float s = 0.f;
        #pragma unroll 16
        for (int i = 0; i < CC; ++i)
            s = fmaf(__ldg(Wup + tid * CC + i), att[i], s);
        uu[tid] = s;
    }
    __syncthreads();
    if (tid < CC) {
        float m = -3.4e38f;
        #pragma unroll 16
        for (int i = 0; i < CC; ++i) m = fmaxf(m, uu[i]);
        float sum = 0.f;
        #pragma unroll 8
        for (int i = 0; i < CC; ++i) sum += expf(uu[i] - m);
        av[tid] = expf(uu[tid] - m) / sum;
    }
    __syncthreads();
    if (is_m1 && (slice == 0) && tid < CC) {   // w_eff for k4 (one block/batch)
        float s = 0.f;
        #pragma unroll 16
        for (int o = 0; o < CC; ++o)
            s = fmaf(av[o], Wq_s[o * CC + tid], s);
        g_weff[b * CC + tid] = s;
    }

    #pragma unroll
    for (int e = tid; e < 512; e += 256) {
        const int rr = e >> 5, cp = e & 31;
        float s0 = 0.f, s1 = 0.f;
        if (is_m1) {
            #pragma unroll 16
            for (int k = 0; k < CC; ++k) {
                const float w = Wo[rr * CC + k];
                s0 = fmaf(w, Wv[k * CC + 2 * cp], s0);
                s1 = fmaf(w, Wv[k * CC + 2 * cp + 1], s1);
            }
        } else {
            #pragma unroll 16
            for (int k = 0; k < CC; ++k) {
                const float w = Wo[rr * CC + k] * av[k];
                s0 = fmaf(w, Wv[k * CC + 2 * cp], s0);
                s1 = fmaf(w, Wv[k * CC + 2 * cp + 1], s1);
            }
        }
        const int r = r0 + rr;                               // row within half
        const int row = 16 * (r >> 3) + (is_m1 ? 0 : 8) + (r & 7);
        float l0, l1;
        const uint32_t hi = bfpack(s0, s1, l0, l1);
        const size_t idx = ((size_t)b * 128 + row) * 32 + cp;
        g_AH[idx] = hi;
        g_AL[idx] = bfpack2(l0, l1);
    }
}

// ---------------- K4: t = w_eff . x per pixel (1024 px/block) ----------------
__global__ void k4_dot(const float* __restrict__ x) {
    const int b = blockIdx.y;
    const int base = blockIdx.x * CHPX1;
    const int tid = threadIdx.x;
    __shared__ float wk[CC];
    if (tid < CC) wk[tid] = g_weff[b * CC + tid];
    __syncthreads();

    float4 a0 = make_float4(0.f, 0.f, 0.f, 0.f);
    #pragma unroll 8
    for (int c = 0; c < CC; ++c) {
        const float w = wk[c];
        const float4 v0 = ((const float4*)(x + ((size_t)b * CC + c) * HWN + base))[tid];
        a0.x = fmaf(w, v0.x, a0.x); a0.y = fmaf(w, v0.y, a0.y);
        a0.z = fmaf(w, v0.z, a0.z); a0.w = fmaf(w, v0.w, a0.w);
    }
    ((float4*)(g_t + (size_t)b * HWN + base))[tid] = a0;
}

// ---------------- K4b: 7x7 conv + sigmoid, SMEM-tiled ------------------------
// 64x16 output tile + 3-px zero halo staged in SMEM. Inner loop is pure
// LDS+FFMA (no bounds checks); each thread computes 4 rows at one x.
__global__ void __launch_bounds__(256)
k4b_conv(const float* __restrict__ Wnorm) {
    __shared__ float ts[CHH * CST];
    __shared__ float wn[49];
    const int b = blockIdx.y;
    const int tile = blockIdx.x;            // 0..63: 4 x-tiles, 16 y-tiles
    const int tx0 = (tile & 3) * CTW;
    const int ty0 = (tile >> 2) * CTH;
    const int tid = threadIdx.x;
    if (tid < 49) wn[tid] = Wnorm[tid];

    // zero halo region (full tile zero-fill, cheap)
    #pragma unroll
    for (int i = tid; i < CHH * CST; i += 256) ts[i] = 0.f;
    __syncthreads();

    // stage tile + halo from g_t
    const float* tb = g_t + (size_t)b * HWN;
    for (int i = tid; i < CHH * CHW; i += 256) {
        const int r = i / CHW, c = i - r * CHW;
        const int gy = ty0 + r - 3, gx = tx0 + c - 3;
        if ((unsigned)gy < 256u && (unsigned)gx < 256u)
            ts[r * CST + c] = tb[gy * 256 + gx];
    }
    __syncthreads();

    // compute: thread -> x = tid&63, rows (tid>>6)*4 .. +3
    const int lx = tid & 63;
    const int ly0 = (tid >> 6) * 4;
    float acc[4] = {0.f, 0.f, 0.f, 0.f};
    #pragma unroll
    for (int ky = 0; ky < 7; ++ky) {
        #pragma unroll
        for (int kx = 0; kx < 7; ++kx) {
            const float w = wn[ky * 7 + kx];
            const float* col = ts + (ly0 + ky) * CST + lx + kx;
            acc[0] = fmaf(w, col[0], acc[0]);
            acc[1] = fmaf(w, col[CST], acc[1]);
            acc[2] = fmaf(w, col[2 * CST], acc[2]);
            acc[3] = fmaf(w, col[3 * CST], acc[3]);
        }
    }
    float* sp = g_s + (size_t)b * HWN + (ty0 + ly0) * 256 + tx0 + lx;
    #pragma unroll
    for (int r = 0; r < 4; ++r)
        sp[r * 256] = 1.f / (1.f + expf(-acc[r]));
}

// ---------------- K5: tensor-core final GEMM, register epilogue (R13) --------
__global__ void __launch_bounds__(256)
k5_mma(const float* __restrict__ x, float* __restrict__ out) {
    __shared__ uint32_t XH[32 * XST];
    __shared__ uint32_t XL[32 * XST];
    __shared__ float ss[256];

    const int b = blockIdx.y;
    const int base0 = blockIdx.x * 256;
    const int tid = threadIdx.x;
    const int lane = tid & 31, w = tid >> 5;
    const int g = lane >> 2, tig = lane & 3;

    uint32_t ah[4][4], al[4][4];
    {
        const uint32_t* AH = g_AH + (size_t)b * 128 * 32;
        const uint32_t* AL = g_AL + (size_t)b * 128 * 32;
        const int r0 = w * 16 + g;
        #pragma unroll
        for (int k = 0; k < 4; ++k) {
            const int cpb = 8 * k + tig;
            ah[k][0] = __ldg(AH + r0 * 32 + cpb);
            ah[k][1] = __ldg(AH + (r0 + 8) * 32 + cpb);
            ah[k][2] = __ldg(AH + r0 * 32 + cpb + 4);
            ah[k][3] = __ldg(AH + (r0 + 8) * 32 + cpb + 4);
            al[k][0] = __ldg(AL + r0 * 32 + cpb);
            al[k][1] = __ldg(AL + (r0 + 8) * 32 + cpb);
            al[k][2] = __ldg(AL + r0 * 32 + cpb + 4);
            al[k][3] = __ldg(AL + (r0 + 8) * 32 + cpb + 4);
        }
    }
    ss[tid] = g_s[(size_t)b * HWN + base0 + tid];

    const float* xb = x + (size_t)b * CC * HWN;
    const int cp0 = tid >> 4,         px0 = (tid & 15) * 4;
    const int cp1 = (tid + 256) >> 4, px1 = (tid & 15) * 4;

    float4 p0a = __ldg((const float4*)(xb + (size_t)(2 * cp0) * HWN + base0 + px0));
    float4 p0b = __ldg((const float4*)(xb + (size_t)(2 * cp0 + 1) * HWN + base0 + px0));
    float4 p1a = __ldg((const float4*)(xb + (size_t)(2 * cp1) * HWN + base0 + px1));
    float4 p1b = __ldg((const float4*)(xb + (size_t)(2 * cp1 + 1) * HWN + base0 + px1));

    for (int st = 0; st < 4; ++st) {
        const int base = base0 + st * 64;

        {
            #pragma unroll
            for (int h = 0; h < 2; ++h) {
                const float4 va = h ? p1a : p0a;
                const float4 vb = h ? p1b : p0b;
                const int cp = h ? cp1 : cp0;
                const int px = h ? px1 : px0;
                const float a0 = va.x, a1 = va.y, a2 = va.z, a3 = va.w;
                const float b0 = vb.x, b1 = vb.y, b2 = vb.z, b3 = vb.w;
                uint4 hh, ll;
                hh.x = prmt_hi(__float_as_uint(a0), __float_as_uint(b0));
                hh.y = prmt_hi(__float_as_uint(a1), __float_as_uint(b1));
                hh.z = prmt_hi(__float_as_uint(a2), __float_as_uint(b2));
                hh.w = prmt_hi(__float_as_uint(a3), __float_as_uint(b3));
                ll.x = cvt_bf16x2(b0 - __uint_as_float(__float_as_uint(b0) & 0xFFFF0000u),
                                  a0 - __uint_as_float(__float_as_uint(a0) & 0xFFFF0000u));
                ll.y = cvt_bf16x2(b1 - __uint_as_float(__float_as_uint(b1) & 0xFFFF0000u),
                                  a1 - __uint_as_float(__float_as_uint(a1) & 0xFFFF0000u));
                ll.z = cvt_bf16x2(b2 - __uint_as_float(__float_as_uint(b2) & 0xFFFF0000u),
                                  a2 - __uint_as_float(__float_as_uint(a2) & 0xFFFF0000u));
                ll.w = cvt_bf16x2(b3 - __uint_as_float(__float_as_uint(b3) & 0xFFFF0000u),
                                  a3 - __uint_as_float(__float_as_uint(a3) & 0xFFFF0000u));
                *(uint4*)(XH + cp * XST + px) = hh;
                *(uint4*)(XL + cp * XST + px) = ll;
            }
        }
        __syncthreads();

        if (st < 3) {
            const int nb = base + 64;
            p0a = __ldg((const float4*)(xb + (size_t)(2 * cp0) * HWN + nb + px0));
            p0b = __ldg((const float4*)(xb + (size_t)(2 * cp0 + 1) * HWN + nb + px0));
            p1a = __ldg((const float4*)(xb + (size_t)(2 * cp1) * HWN + nb + px1));
            p1b = __ldg((const float4*)(xb + (size_t)(2 * cp1 + 1) * HWN + nb + px1));
        }

        const int orow = 8 * w + g;
        float* orp = out + ((size_t)b * CC + orow) * HWN + base;
        const float* sb = ss + st * 64;
        #pragma unroll
        for (int n = 0; n < 8; ++n) {
            float d0 = 0.f, d1 = 0.f, d2 = 0.f, d3 = 0.f;
            const int pxg = 8 * n + g;
            #pragma unroll
            for (int k = 0; k < 4; ++k) {
                const uint32_t bh0 = XH[(8 * k + tig) * XST + pxg];
                const uint32_t bh1 = XH[(8 * k + tig + 4) * XST + pxg];
                const uint32_t bl0 = XL[(8 * k + tig) * XST + pxg];
                const uint32_t bl1 = XL[(8 * k + tig + 4) * XST + pxg];
                MMA16816(d0, d1, d2, d3, ah[k][0], ah[k][1], ah[k][2], ah[k][3], bh0, bh1);
                MMA16816(d0, d1, d2, d3, ah[k][0], ah[k][1], ah[k][2], ah[k][3], bl0, bl1);
                MMA16816(d0, d1, d2, d3, al[k][0], al[k][1], al[k][2], al[k][3], bh0, bh1);
            }
            const int col = 8 * n + 2 * tig;
            const float2 sv = *(const float2*)(sb + col);
            float2 o2;
            o2.x = fmaf(sv.x, d0, d2);
            o2.y = fmaf(sv.y, d1, d3);
            *(float2*)(orp + col) = o2;
        }
        __syncthreads();
    }
}

// ---------------- launch ------------------------------------------------------
extern "C" void kernel_launch(void* const* d_in, const int* in_sizes, int n_in,
                              void* d_out, int out_size) {
    const float* x      = (const float*)d_in[0];
    const float* Wq     = (const float*)d_in[1];
    const float* Wk     = (const float*)d_in[2];
    const float* Wv_spe = (const float*)d_in[3];
    const float* Wv_spa = (const float*)d_in[4];
    const float* Wup    = (const float*)d_in[5];
    const float* Wout   = (const float*)d_in[6];
    const float* Wnorm  = (const float*)d_in[7];
    float* out = (float*)d_out;

    static int attr_set = 0;
    if (!attr_set) {
        cudaFuncSetAttribute(k12_fused,
                             cudaFuncAttributeMaxDynamicSharedMemorySize, K12_SMEM);
        attr_set = 1;
    }

    k12_fused<<<dim3(NCHK, BB), 256, K12_SMEM>>>(x, Wk);
    k3b_fused<<<64, 256>>>(Wq, Wup, Wout, Wv_spe, Wv_spa);
    k4_dot<<<dim3(NCHK, BB), 256>>>(x);
    k4b_conv<<<dim3(64, BB), 256>>>(Wnorm);
    k5_mma<<<dim3(HWN / 256, BB), 256>>>(x, out);
}

// round 17
// speedup vs baseline: 1.2324x; 1.1396x over previous
#include <cuda_runtime.h>
#include <cuda_bf16.h>
#include <cstdint>
#include <math.h>

// Problem constants
#define BB 8
#define CC 64
#define HWN 65536
#define NCHK 64                // chunks (1024 px each) for k12/k4
#define CHPX1 1024
#define SUBPX 128              // k12 smem subtile width (single-wave occupancy)

typedef unsigned long long ull;

// ---- k12 smem layout (floats): xs 64*128, es 128, red 8 ----
#define K12_XS    0                     // 8192 floats
#define K12_ES    8192                  // 128
#define K12_RED   8320                  // 8
#define K12_SMEM  (8328 * 4)            // ~33 KB -> 6 blocks/SM -> 1 wave

// ---- k5: X tile row stride (u32 words). 72%32==8 -> conflict-free B reads ----
#define XST      72
#define K5PX     512           // pixels per k5 block (8 subtiles, 1 wave)

// ---- k4b conv tiling: 64x16 outputs, 3-px halo ----
#define CTW      64
#define CTH      16
#define CHW      70
#define CHH      22
#define CST      72

// ---------------- scratch (device globals) -----------------------------------
__device__ float g_t[BB * HWN];           // pre-conv spatial attention
__device__ float g_s[BB * HWN];           // sigmoid(conv(t))
__device__ float g_Zpart[BB * NCHK];
__device__ float g_pooledpart[BB * NCHK * CC];
__device__ float g_weff[BB * CC];         // a^T Wq
// Row-interleaved stacked A: tile w rows [16w,16w+8) = M1[8w..8w+8),
// rows [16w+8,16w+16) = M2[8w..8w+8). bf16x2 pair-packed over input channel.
__device__ uint32_t g_AH[BB * 128 * 32];  // hi part
__device__ uint32_t g_AL[BB * 128 * 32];  // lo part

// ---------------- mma.sync m16n8k16 bf16 -------------------------------------
#define MMA16816(d0, d1, d2, d3, a0, a1, a2, a3, b0, b1)                     \
    asm volatile(                                                            \
        "mma.sync.aligned.m16n8k16.row.col.f32.bf16.bf16.f32 "               \
        "{%0,%1,%2,%3}, {%4,%5,%6,%7}, {%8,%9}, {%0,%1,%2,%3};"              \
        : "+f"(d0), "+f"(d1), "+f"(d2), "+f"(d3)                             \
        : "r"(a0), "r"(a1), "r"(a2), "r"(a3), "r"(b0), "r"(b1))

__device__ __forceinline__ uint32_t bfpack(float v0, float v1,
                                           float& l0, float& l1) {
    __nv_bfloat16 h0 = __float2bfloat16_rn(v0);
    __nv_bfloat16 h1 = __float2bfloat16_rn(v1);
    l0 = v0 - __bfloat162float(h0);
    l1 = v1 - __bfloat162float(h1);
    return (uint32_t)__bfloat16_as_ushort(h0) |
           ((uint32_t)__bfloat16_as_ushort(h1) << 16);
}
__device__ __forceinline__ uint32_t bfpack2(float v0, float v1) {
    return (uint32_t)__bfloat16_as_ushort(__float2bfloat16_rn(v0)) |
           ((uint32_t)__bfloat16_as_ushort(__float2bfloat16_rn(v1)) << 16);
}
// Truncation split: hi = top-16-bits of each fp32 (exact bf16), packed by PRMT.
__device__ __forceinline__ uint32_t prmt_hi(uint32_t u0, uint32_t u1) {
    uint32_t r;
    asm("prmt.b32 %0, %1, %2, 0x7632;" : "=r"(r) : "r"(u0), "r"(u1));
    return r;
}
// d = { lo half = bf16(lo), hi half = bf16(hi) }
__device__ __forceinline__ uint32_t cvt_bf16x2(float hi, float lo) {
    uint32_t r;
    asm("cvt.rn.bf16x2.f32 %0, %1, %2;" : "=r"(r) : "f"(hi), "f"(lo));
    return r;
}

// ---------------- K12: fused exp(k logits) + weighted pooling ----------------
// ONE DRAM pass over x. 128-px subtiles; ~33 KB smem -> 6 blocks/SM -> 1 wave.
__global__ void __launch_bounds__(256)
k12_fused(const float* __restrict__ x, const float* __restrict__ Wk) {
    extern __shared__ float sh[];
    float* xs  = sh + K12_XS;
    float* es  = sh + K12_ES;
    float* red = sh + K12_RED;
    __shared__ float wk[CC];

    const int b = blockIdx.y;
    const int chunk = blockIdx.x;
    const int base = chunk * CHPX1;
    const int tid = threadIdx.x;
    const int wid = tid >> 5, lid = tid & 31;
    if (tid < CC) wk[tid] = Wk[tid];

    const float* xb = x + (size_t)b * CC * HWN;
    float zacc = 0.f;
    float pacc[8];
    #pragma unroll
    for (int j = 0; j < 8; ++j) pacc[j] = 0.f;

    for (int s = 0; s < CHPX1 / SUBPX; ++s) {
        const int pbase = base + s * SUBPX;
        __syncthreads();    // xs/es safe to overwrite (covers wk on s=0)
        // stage x tile: 64ch x 128px = 2048 float4, 8 per thread
        #pragma unroll
        for (int i = tid; i < 2048; i += 256) {
            const int c = i >> 5, k = i & 31;
            ((float4*)(xs + c * SUBPX))[k] =
                __ldg((const float4*)(xb + (size_t)c * HWN + pbase) + k);
        }
        __syncthreads();
        // logits + exp: threads 0..127 handle one pixel each
        if (tid < SUBPX) {
            float lg = 0.f;
            #pragma unroll 16
            for (int c = 0; c < CC; ++c)
                lg = fmaf(wk[c], xs[c * SUBPX + tid], lg);
            const float e = expf(lg);
            es[tid] = e;
            zacc += e;
        }
        __syncthreads();
        // pooling: warp wid -> channels [8wid, 8wid+8), one float4 per lane
        #pragma unroll
        for (int j = 0; j < 8; ++j) {
            const int c = wid * 8 + j;
            const float4 v = ((const float4*)(xs + c * SUBPX))[lid];
            const float4 e4 = ((const float4*)es)[lid];
            pacc[j] += v.x * e4.x + v.y * e4.y + v.z * e4.z + v.w * e4.w;
        }
    }

    #pragma unroll
    for (int j = 0; j < 8; ++j) {
        #pragma unroll
        for (int off = 16; off; off >>= 1)
            pacc[j] += __shfl_xor_sync(0xffffffffu, pacc[j], off);
    }
    if (lid == 0) {
        #pragma unroll
        for (int j = 0; j < 8; ++j)
            g_pooledpart[((size_t)b * NCHK + chunk) * CC + wid * 8 + j] = pacc[j];
    }
    #pragma unroll
    for (int off = 16; off; off >>= 1)
        zacc += __shfl_xor_sync(0xffffffffu, zacc, off);
    if (lid == 0 && wid < 4) red[wid] = zacc;    // only warps 0-3 hold z
    __syncthreads();
    if (tid == 0) {
        float zz = 0.f;
        #pragma unroll
        for (int w = 0; w < 4; ++w) zz += red[w];
        g_Zpart[b * NCHK + chunk] = zz;
    }
}

// ---------------- K3B: fused channel-attention chain + stacked A build -------
__global__ void __launch_bounds__(256)
k3b_fused(const float* __restrict__ Wq, const float* __restrict__ Wup,
          const float* __restrict__ Wout,
          const float* __restrict__ Wv_spe, const float* __restrict__ Wv_spa) {
    const int blk = blockIdx.x;           // 0..63
    const int b = blk >> 3, slice = blk & 7;
    const bool is_m1 = slice < 4;
    const int r0 = (slice & 3) * 16;
    const int tid = threadIdx.x;          // 256

    __shared__ float Wq_s[CC * CC];
    __shared__ float Wv[CC * CC];
    __shared__ float Wo[16 * CC];
    __shared__ float pooled[CC];
    __shared__ float att[CC];
    __shared__ float uu[CC];
    __shared__ float av[CC];
    __shared__ float zsh;

    const float* wvsrc = is_m1 ? Wv_spa : Wv_spe;
    for (int i = tid; i < CC * CC / 4; i += 256) {
        ((float4*)Wq_s)[i] = ((const float4*)Wq)[i];
        ((float4*)Wv)[i]   = ((const float4*)wvsrc)[i];
    }
    if (tid < 16 * CC / 4)
        ((float4*)Wo)[tid] = ((const float4*)(Wout + r0 * CC))[tid];

    if (tid < CC) {
        float s = 0.f;
        #pragma unroll 16
        for (int ch = 0; ch < NCHK; ++ch)
            s += g_pooledpart[((size_t)b * NCHK + ch) * CC + tid];
        pooled[tid] = s;
    }
    if (tid == 0) {
        float z = 0.f;
        #pragma unroll 16
        for (int ch = 0; ch < NCHK; ++ch) z += g_Zpart[b * NCHK + ch];
        zsh = z;
    }
    __syncthreads();
    if (tid < CC) {
        const float inv = 1.f / zsh;
        float s = 0.f;
        #pragma unroll 16
        for (int i = 0; i < CC; ++i)
            s = fmaf(Wq_s[tid * CC + i], pooled[i], s);
        att[tid] = s * inv;
    }
    __syncthreads();
    if (tid < CC) {
        float s = 0.f;
        #pragma unroll 16
        for (int i = 0; i < CC; ++i)
            s = fmaf(__ldg(Wup + tid * CC + i), att[i], s);
        uu[tid] = s;
    }
    __syncthreads();
    if (tid < CC) {
        float m = -3.4e38f;
        #pragma unroll 16
        for (int i = 0; i < CC; ++i) m = fmaxf(m, uu[i]);
        float sum = 0.f;
        #pragma unroll 8
        for (int i = 0; i < CC; ++i) sum += expf(uu[i] - m);
        av[tid] = expf(uu[tid] - m) / sum;
    }
    __syncthreads();
    if (is_m1 && (slice == 0) && tid < CC) {
        float s = 0.f;
        #pragma unroll 16
        for (int o = 0; o < CC; ++o)
            s = fmaf(av[o], Wq_s[o * CC + tid], s);
        g_weff[b * CC + tid] = s;
    }

    #pragma unroll
    for (int e = tid; e < 512; e += 256) {
        const int rr = e >> 5, cp = e & 31;
        float s0 = 0.f, s1 = 0.f;
        if (is_m1) {
            #pragma unroll 16
            for (int k = 0; k < CC; ++k) {
                const float w = Wo[rr * CC + k];
                s0 = fmaf(w, Wv[k * CC + 2 * cp], s0);
                s1 = fmaf(w, Wv[k * CC + 2 * cp + 1], s1);
            }
        } else {
            #pragma unroll 16
            for (int k = 0; k < CC; ++k) {
                const float w = Wo[rr * CC + k] * av[k];
                s0 = fmaf(w, Wv[k * CC + 2 * cp], s0);
                s1 = fmaf(w, Wv[k * CC + 2 * cp + 1], s1);
            }
        }
        const int r = r0 + rr;
        const int row = 16 * (r >> 3) + (is_m1 ? 0 : 8) + (r & 7);
        float l0, l1;
        const uint32_t hi = bfpack(s0, s1, l0, l1);
        const size_t idx = ((size_t)b * 128 + row) * 32 + cp;
        g_AH[idx] = hi;
        g_AL[idx] = bfpack2(l0, l1);
    }
}

// ---------------- K4: t = w_eff . x per pixel (1024 px/block) ----------------
__global__ void k4_dot(const float* __restrict__ x) {
    const int b = blockIdx.y;
    const int base = blockIdx.x * CHPX1;
    const int tid = threadIdx.x;
    __shared__ float wk[CC];
    if (tid < CC) wk[tid] = g_weff[b * CC + tid];
    __syncthreads();

    float4 a0 = make_float4(0.f, 0.f, 0.f, 0.f);
    #pragma unroll 8
    for (int c = 0; c < CC; ++c) {
        const float w = wk[c];
        const float4 v0 = ((const float4*)(x + ((size_t)b * CC + c) * HWN + base))[tid];
        a0.x = fmaf(w, v0.x, a0.x); a0.y = fmaf(w, v0.y, a0.y);
        a0.z = fmaf(w, v0.z, a0.z); a0.w = fmaf(w, v0.w, a0.w);
    }
    ((float4*)(g_t + (size_t)b * HWN + base))[tid] = a0;
}

// ---------------- K4b: 7x7 conv + sigmoid, SMEM-tiled ------------------------
__global__ void __launch_bounds__(256)
k4b_conv(const float* __restrict__ Wnorm) {
    __shared__ float ts[CHH * CST];
    __shared__ float wn[49];
    const int b = blockIdx.y;
    const int tile = blockIdx.x;
    const int tx0 = (tile & 3) * CTW;
    const int ty0 = (tile >> 2) * CTH;
    const int tid = threadIdx.x;
    if (tid < 49) wn[tid] = Wnorm[tid];

    #pragma unroll
    for (int i = tid; i < CHH * CST; i += 256) ts[i] = 0.f;
    __syncthreads();

    const float* tb = g_t + (size_t)b * HWN;
    for (int i = tid; i < CHH * CHW; i += 256) {
        const int r = i / CHW, c = i - r * CHW;
        const int gy = ty0 + r - 3, gx = tx0 + c - 3;
        if ((unsigned)gy < 256u && (unsigned)gx < 256u)
            ts[r * CST + c] = tb[gy * 256 + gx];
    }
    __syncthreads();

    const int lx = tid & 63;
    const int ly0 = (tid >> 6) * 4;
    float acc[4] = {0.f, 0.f, 0.f, 0.f};
    #pragma unroll
    for (int ky = 0; ky < 7; ++ky) {
        #pragma unroll
        for (int kx = 0; kx < 7; ++kx) {
            const float w = wn[ky * 7 + kx];
            const float* col = ts + (ly0 + ky) * CST + lx + kx;
            acc[0] = fmaf(w, col[0], acc[0]);
            acc[1] = fmaf(w, col[CST], acc[1]);
            acc[2] = fmaf(w, col[2 * CST], acc[2]);
            acc[3] = fmaf(w, col[3 * CST], acc[3]);
        }
    }
    float* sp = g_s + (size_t)b * HWN + (ty0 + ly0) * 256 + tx0 + lx;
    #pragma unroll
    for (int r = 0; r < 4; ++r)
        sp[r * 256] = 1.f / (1.f + expf(-acc[r]));
}

// ---------------- K5: tensor-core final GEMM, 512 px/block (1 wave) ----------
__global__ void __launch_bounds__(256)
k5_mma(const float* __restrict__ x, float* __restrict__ out) {
    __shared__ uint32_t XH[32 * XST];
    __shared__ uint32_t XL[32 * XST];
    __shared__ float ss[K5PX];

    const int b = blockIdx.y;
    const int base0 = blockIdx.x * K5PX;
    const int tid = threadIdx.x;
    const int lane = tid & 31, w = tid >> 5;
    const int g = lane >> 2, tig = lane & 3;

    uint32_t ah[4][4], al[4][4];
    {
        const uint32_t* AH = g_AH + (size_t)b * 128 * 32;
        const uint32_t* AL = g_AL + (size_t)b * 128 * 32;
        const int r0 = w * 16 + g;
        #pragma unroll
        for (int k = 0; k < 4; ++k) {
            const int cpb = 8 * k + tig;
            ah[k][0] = __ldg(AH + r0 * 32 + cpb);
            ah[k][1] = __ldg(AH + (r0 + 8) * 32 + cpb);
            ah[k][2] = __ldg(AH + r0 * 32 + cpb + 4);
            ah[k][3] = __ldg(AH + (r0 + 8) * 32 + cpb + 4);
            al[k][0] = __ldg(AL + r0 * 32 + cpb);
            al[k][1] = __ldg(AL + (r0 + 8) * 32 + cpb);
            al[k][2] = __ldg(AL + r0 * 32 + cpb + 4);
            al[k][3] = __ldg(AL + (r0 + 8) * 32 + cpb + 4);
        }
    }
    ss[tid] = g_s[(size_t)b * HWN + base0 + tid];
    ss[tid + 256] = g_s[(size_t)b * HWN + base0 + tid + 256];

    const float* xb = x + (size_t)b * CC * HWN;
    const int cp0 = tid >> 4,         px0 = (tid & 15) * 4;
    const int cp1 = (tid + 256) >> 4, px1 = (tid & 15) * 4;

    float4 p0a = __ldg((const float4*)(xb + (size_t)(2 * cp0) * HWN + base0 + px0));
    float4 p0b = __ldg((const float4*)(xb + (size_t)(2 * cp0 + 1) * HWN + base0 + px0));
    float4 p1a = __ldg((const float4*)(xb + (size_t)(2 * cp1) * HWN + base0 + px1));
    float4 p1b = __ldg((const float4*)(xb + (size_t)(2 * cp1 + 1) * HWN + base0 + px1));

    for (int st = 0; st < K5PX / 64; ++st) {
        const int base = base0 + st * 64;

        {
            #pragma unroll
            for (int h = 0; h < 2; ++h) {
                const float4 va = h ? p1a : p0a;
                const float4 vb = h ? p1b : p0b;
                const int cp = h ? cp1 : cp0;
                const int px = h ? px1 : px0;
                const float a0 = va.x, a1 = va.y, a2 = va.z, a3 = va.w;
                const float b0 = vb.x, b1 = vb.y, b2 = vb.z, b3 = vb.w;
                uint4 hh, ll;
                hh.x = prmt_hi(__float_as_uint(a0), __float_as_uint(b0));
                hh.y = prmt_hi(__float_as_uint(a1), __float_as_uint(b1));
                hh.z = prmt_hi(__float_as_uint(a2), __float_as_uint(b2));
                hh.w = prmt_hi(__float_as_uint(a3), __float_as_uint(b3));
                ll.x = cvt_bf16x2(b0 - __uint_as_float(__float_as_uint(b0) & 0xFFFF0000u),
                                  a0 - __uint_as_float(__float_as_uint(a0) & 0xFFFF0000u));
                ll.y = cvt_bf16x2(b1 - __uint_as_float(__float_as_uint(b1) & 0xFFFF0000u),
                                  a1 - __uint_as_float(__float_as_uint(a1) & 0xFFFF0000u));
                ll.z = cvt_bf16x2(b2 - __uint_as_float(__float_as_uint(b2) & 0xFFFF0000u),
                                  a2 - __uint_as_float(__float_as_uint(a2) & 0xFFFF0000u));
                ll.w = cvt_bf16x2(b3 - __uint_as_float(__float_as_uint(b3) & 0xFFFF0000u),
                                  a3 - __uint_as_float(__float_as_uint(a3) & 0xFFFF0000u));
                *(uint4*)(XH + cp * XST + px) = hh;
                *(uint4*)(XL + cp * XST + px) = ll;
            }
        }
        __syncthreads();

        if (st < K5PX / 64 - 1) {
            const int nb = base + 64;
            p0a = __ldg((const float4*)(xb + (size_t)(2 * cp0) * HWN + nb + px0));
            p0b = __ldg((const float4*)(xb + (size_t)(2 * cp0 + 1) * HWN + nb + px0));
            p1a = __ldg((const float4*)(xb + (size_t)(2 * cp1) * HWN + nb + px1));
            p1b = __ldg((const float4*)(xb + (size_t)(2 * cp1 + 1) * HWN + nb + px1));
        }

        const int orow = 8 * w + g;
        float* orp = out + ((size_t)b * CC + orow) * HWN + base;
        const float* sb = ss + st * 64;
        #pragma unroll
        for (int n = 0; n < 8; ++n) {
            float d0 = 0.f, d1 = 0.f, d2 = 0.f, d3 = 0.f;
            const int pxg = 8 * n + g;
            #pragma unroll
            for (int k = 0; k < 4; ++k) {
                const uint32_t bh0 = XH[(8 * k + tig) * XST + pxg];
                const uint32_t bh1 = XH[(8 * k + tig + 4) * XST + pxg];
                const uint32_t bl0 = XL[(8 * k + tig) * XST + pxg];
                const uint32_t bl1 = XL[(8 * k + tig + 4) * XST + pxg];
                MMA16816(d0, d1, d2, d3, ah[k][0], ah[k][1], ah[k][2], ah[k][3], bh0, bh1);
                MMA16816(d0, d1, d2, d3, ah[k][0], ah[k][1], ah[k][2], ah[k][3], bl0, bl1);
                MMA16816(d0, d1, d2, d3, al[k][0], al[k][1], al[k][2], al[k][3], bh0, bh1);
            }
            const int col = 8 * n + 2 * tig;
            const float2 sv = *(const float2*)(sb + col);
            float2 o2;
            o2.x = fmaf(sv.x, d0, d2);
            o2.y = fmaf(sv.y, d1, d3);
            *(float2*)(orp + col) = o2;
        }
        __syncthreads();
    }
}

// ---------------- launch ------------------------------------------------------
extern "C" void kernel_launch(void* const* d_in, const int* in_sizes, int n_in,
                              void* d_out, int out_size) {
    const float* x      = (const float*)d_in[0];
    const float* Wq     = (const float*)d_in[1];
    const float* Wk     = (const float*)d_in[2];
    const float* Wv_spe = (const float*)d_in[3];
    const float* Wv_spa = (const float*)d_in[4];
    const float* Wup    = (const float*)d_in[5];
    const float* Wout   = (const float*)d_in[6];
    const float* Wnorm  = (const float*)d_in[7];
    float* out = (float*)d_out;

    static int attr_set = 0;
    if (!attr_set) {
        cudaFuncSetAttribute(k12_fused,
                             cudaFuncAttributeMaxDynamicSharedMemorySize, K12_SMEM);
        attr_set = 1;
    }

    k12_fused<<<dim3(NCHK, BB), 256, K12_SMEM>>>(x, Wk);
    k3b_fused<<<64, 256>>>(Wq, Wup, Wout, Wv_spe, Wv_spa);
    k4_dot<<<dim3(NCHK, BB), 256>>>(x);
    k4b_conv<<<dim3(64, BB), 256>>>(Wnorm);
    k5_mma<<<dim3(HWN / K5PX, BB), 256>>>(x, out);
}